// round 1
// baseline (speedup 1.0000x reference)
#include <cuda_runtime.h>
#include <cuda_bf16.h>
#include <math.h>

// ---------------------------------------------------------------------------
// Problem constants (fixed shapes from the dataset)
// ---------------------------------------------------------------------------
#define NN       262144      // total nodes
#define NE       2097152     // edges
#define F_IN     64
#define C1       128
#define C2       96
#define BATCH    4096
#define NODES    64          // nodes per graph
#define IN_MLP   6144        // C2 * NODES
#define HID      2048
#define HID4     512
#define OUTF     256
#define NEG_SLOPE 0.01f
#define EPS      1e-5f

// ---------------------------------------------------------------------------
// Scratch (static device globals -- no allocation allowed)
// ---------------------------------------------------------------------------
__device__ float g_rs_out[NN];             // degree accum -> rsqrt(deg_out)
__device__ float g_rs_in [NN];             // degree accum -> rsqrt(deg_in)
__device__ float g_agg1  [(size_t)NN * F_IN];   // 64 MB
__device__ float g_g1    [(size_t)NN * C1];     // 128 MB
__device__ float g_h2    [(size_t)NN * C2];     // 96 MB
__device__ float g_agg2  [(size_t)NN * C2];     // 96 MB
__device__ float g_m1    [(size_t)BATCH * HID]; // 32 MB
__device__ float g_m2    [(size_t)BATCH * HID4];// 8 MB

// ---------------------------------------------------------------------------
// Utility kernels
// ---------------------------------------------------------------------------
__global__ void zero_kernel(float* __restrict__ p, size_t n) {
    size_t i = (size_t)blockIdx.x * blockDim.x + threadIdx.x;
    size_t stride = (size_t)gridDim.x * blockDim.x;
    for (; i < n; i += stride) p[i] = 0.0f;
}

__global__ void deg_kernel(const int* __restrict__ src, const int* __restrict__ dst,
                           int E, float* __restrict__ dout, float* __restrict__ din) {
    int i = blockIdx.x * blockDim.x + threadIdx.x;
    if (i < E) {
        atomicAdd(&dout[src[i]], 1.0f);
        atomicAdd(&din [dst[i]], 1.0f);
    }
}

__global__ void rsqrt_deg_kernel(float* __restrict__ a, float* __restrict__ b, int n) {
    int i = blockIdx.x * blockDim.x + threadIdx.x;
    if (i < n) {
        a[i] = rsqrtf(fmaxf(a[i], 1.0f));
        b[i] = rsqrtf(fmaxf(b[i], 1.0f));
    }
}

// Scatter for conv1: agg1[dst] += x[src] * rs_out[src] * ew   (64 feats, one warp/edge)
__global__ void scatter1_kernel(const float* __restrict__ x, const float* __restrict__ ew,
                                const int* __restrict__ src, const int* __restrict__ dst,
                                const float* __restrict__ rs_out, float* __restrict__ agg,
                                int E) {
    int e = blockIdx.x * 8 + (threadIdx.x >> 5);
    if (e >= E) return;
    int lane = threadIdx.x & 31;
    int s = src[e], d = dst[e];
    float w = ew[e] * rs_out[s];
    float2 v = reinterpret_cast<const float2*>(x)[(size_t)s * 32 + lane];
    float* base = agg + (size_t)d * 64 + 2 * lane;
    atomicAdd(base,     v.x * w);
    atomicAdd(base + 1, v.y * w);
}

// Scatter for conv2: agg2[dst] += h2[src] * ew   (96 feats, one warp/edge; rs_out folded in GEMM)
__global__ void scatter2_kernel(const float* __restrict__ h, const float* __restrict__ ew,
                                const int* __restrict__ src, const int* __restrict__ dst,
                                float* __restrict__ agg, int E) {
    int e = blockIdx.x * 8 + (threadIdx.x >> 5);
    if (e >= E) return;
    int lane = threadIdx.x & 31;
    int s = src[e], d = dst[e];
    float w = ew[e];
    const float* hp = h + (size_t)s * 96;
    float* ap = agg + (size_t)d * 96;
#pragma unroll
    for (int i = 0; i < 3; i++) {
        int c = lane + 32 * i;
        atomicAdd(&ap[c], hp[c] * w);
    }
}

// ---------------------------------------------------------------------------
// SGEMM: C[M,N] = A[M,K] @ B[K,N], optional per-row scale + leaky relu epilogue
// 128x128 block tile, 8x8 thread tile, BK=8, 256 threads.
// ---------------------------------------------------------------------------
__global__ __launch_bounds__(256)
void sgemm_kernel(int M, int N, int K,
                  const float* __restrict__ A, const float* __restrict__ B,
                  float* __restrict__ C,
                  const float* __restrict__ rowscale, int do_leaky) {
    const int BM = 128, BN = 128, BK = 8, TM = 8, TN = 8;
    __shared__ float As[BK][BM];
    __shared__ float Bs[BK][BN];

    int tid = threadIdx.x;
    int block_row = blockIdx.y * BM;
    int block_col = blockIdx.x * BN;

    int trow = (tid / (BN / TN)) * TM;   // 0..120 step 8
    int tcol = (tid % (BN / TN)) * TN;   // 0..120 step 8

    float acc[TM][TN];
#pragma unroll
    for (int i = 0; i < TM; i++)
#pragma unroll
        for (int j = 0; j < TN; j++) acc[i][j] = 0.0f;

    // load mapping
    int arow = tid >> 1;            // 0..127
    int acol0 = (tid & 1) * 4;      // 0 or 4
    int brow = tid >> 5;            // 0..7
    int bcol0 = (tid & 31) * 4;     // 0..124

    float ra[TM], rb[TN];

    for (int k0 = 0; k0 < K; k0 += BK) {
        // A tile: 128 x 8
        {
            int gr = block_row + arow;
#pragma unroll
            for (int i = 0; i < 4; i++) {
                int gc = k0 + acol0 + i;
                float v = 0.0f;
                if (gr < M && gc < K) v = A[(size_t)gr * K + gc];
                As[acol0 + i][arow] = v;
            }
        }
        // B tile: 8 x 128
        {
            int gr = k0 + brow;
#pragma unroll
            for (int i = 0; i < 4; i++) {
                int gc = block_col + bcol0 + i;
                float v = 0.0f;
                if (gr < K && gc < N) v = B[(size_t)gr * N + gc];
                Bs[brow][bcol0 + i] = v;
            }
        }
        __syncthreads();
#pragma unroll
        for (int kk = 0; kk < BK; kk++) {
#pragma unroll
            for (int i = 0; i < TM; i++) ra[i] = As[kk][trow + i];
#pragma unroll
            for (int j = 0; j < TN; j++) rb[j] = Bs[kk][tcol + j];
#pragma unroll
            for (int i = 0; i < TM; i++)
#pragma unroll
                for (int j = 0; j < TN; j++)
                    acc[i][j] = fmaf(ra[i], rb[j], acc[i][j]);
        }
        __syncthreads();
    }

#pragma unroll
    for (int i = 0; i < TM; i++) {
        int gr = block_row + trow + i;
        if (gr >= M) continue;
        float s = rowscale ? rowscale[gr] : 1.0f;
#pragma unroll
        for (int j = 0; j < TN; j++) {
            int gc = block_col + tcol + j;
            if (gc >= N) continue;
            float v = acc[i][j] * s;
            if (do_leaky) v = (v >= 0.0f) ? v : NEG_SLOPE * v;
            C[(size_t)gr * N + gc] = v;
        }
    }
}

// ---------------------------------------------------------------------------
// GraphNorm: one block per graph (64 nodes x C channels), in place.
// Optional pre-op: multiply row by rs_in[node], then leaky relu, before norm.
// ---------------------------------------------------------------------------
__global__ void graphnorm_kernel(float* __restrict__ h, int C,
                                 const float* __restrict__ alpha,
                                 const float* __restrict__ gamma,
                                 const float* __restrict__ beta,
                                 const float* __restrict__ rs_in, int pre_leaky) {
    extern __shared__ float sm[];   // NODES * C
    int g = blockIdx.x;
    float* base = h + (size_t)g * NODES * C;
    int tid = threadIdx.x;

    for (int idx = tid; idx < NODES * C; idx += blockDim.x) {
        int r = idx / C;
        float v = base[idx];
        if (rs_in) v *= rs_in[g * NODES + r];
        if (pre_leaky) v = (v >= 0.0f) ? v : NEG_SLOPE * v;
        sm[idx] = v;
    }
    __syncthreads();

    for (int c = tid; c < C; c += blockDim.x) {
        float sum = 0.0f;
#pragma unroll 8
        for (int r = 0; r < NODES; r++) sum += sm[r * C + c];
        float mean = sum * (1.0f / NODES);
        float a = alpha[c];
        float am = a * mean;
        float var = 0.0f;
#pragma unroll 8
        for (int r = 0; r < NODES; r++) {
            float s = sm[r * C + c] - am;
            var += s * s;
        }
        var *= (1.0f / NODES);
        float inv = rsqrtf(var + EPS);
        float gmm = gamma[c], bt = beta[c];
        for (int r = 0; r < NODES; r++)
            base[r * C + c] = gmm * (sm[r * C + c] - am) * inv + bt;
    }
}

// ---------------------------------------------------------------------------
// InstanceNorm1d (affine=False) per row, in place. One block per row.
// ---------------------------------------------------------------------------
__global__ void instnorm_kernel(float* __restrict__ h, int C) {
    int row = blockIdx.x;
    float* p = h + (size_t)row * C;
    int tid = threadIdx.x;

    float s = 0.0f, q = 0.0f;
    for (int c = tid; c < C; c += blockDim.x) {
        float v = p[c];
        s += v; q += v * v;
    }
    __shared__ float ss[32], sq[32];
#pragma unroll
    for (int o = 16; o; o >>= 1) {
        s += __shfl_xor_sync(0xffffffffu, s, o);
        q += __shfl_xor_sync(0xffffffffu, q, o);
    }
    if ((tid & 31) == 0) { ss[tid >> 5] = s; sq[tid >> 5] = q; }
    __syncthreads();
    int nwarp = blockDim.x >> 5;
    if (tid < 32) {
        s = (tid < nwarp) ? ss[tid] : 0.0f;
        q = (tid < nwarp) ? sq[tid] : 0.0f;
#pragma unroll
        for (int o = 16; o; o >>= 1) {
            s += __shfl_xor_sync(0xffffffffu, s, o);
            q += __shfl_xor_sync(0xffffffffu, q, o);
        }
        if (tid == 0) { ss[0] = s; sq[0] = q; }
    }
    __syncthreads();
    float mean = ss[0] / C;
    float var = sq[0] / C - mean * mean;
    float inv = rsqrtf(var + EPS);
    for (int c = tid; c < C; c += blockDim.x)
        p[c] = (p[c] - mean) * inv;
}

// ---------------------------------------------------------------------------
// Launch
// ---------------------------------------------------------------------------
static void launch_sgemm(int M, int N, int K, const float* A, const float* B,
                         float* C, const float* rowscale, int do_leaky) {
    dim3 grid((N + 127) / 128, (M + 127) / 128);
    sgemm_kernel<<<grid, 256>>>(M, N, K, A, B, C, rowscale, do_leaky);
}

extern "C" void kernel_launch(void* const* d_in, const int* in_sizes, int n_in,
                              void* d_out, int out_size) {
    const float* x    = (const float*)d_in[0];
    const float* ew   = (const float*)d_in[1];
    const int*   src  = (const int*)  d_in[2];
    const int*   dst  = (const int*)  d_in[3];
    const float* W1   = (const float*)d_in[4];
    const float* W2   = (const float*)d_in[5];
    const float* a1   = (const float*)d_in[6];
    const float* gm1  = (const float*)d_in[7];
    const float* bt1  = (const float*)d_in[8];
    const float* a2   = (const float*)d_in[9];
    const float* gm2  = (const float*)d_in[10];
    const float* bt2  = (const float*)d_in[11];
    const float* Win  = (const float*)d_in[12];
    const float* Whid = (const float*)d_in[13];
    const float* Wcls = (const float*)d_in[14];
    float* out = (float*)d_out;

    const int E = in_sizes[1];   // 2097152
    const int N = in_sizes[0] / F_IN; // 262144

    float *rs_out_p, *rs_in_p, *agg1_p, *g1_p, *h2_p, *agg2_p, *m1_p, *m2_p;
    cudaGetSymbolAddress((void**)&rs_out_p, g_rs_out);
    cudaGetSymbolAddress((void**)&rs_in_p,  g_rs_in);
    cudaGetSymbolAddress((void**)&agg1_p,   g_agg1);
    cudaGetSymbolAddress((void**)&g1_p,     g_g1);
    cudaGetSymbolAddress((void**)&h2_p,     g_h2);
    cudaGetSymbolAddress((void**)&agg2_p,   g_agg2);
    cudaGetSymbolAddress((void**)&m1_p,     g_m1);
    cudaGetSymbolAddress((void**)&m2_p,     g_m2);

    // 0) zero accumulators
    zero_kernel<<<2048, 256>>>(rs_out_p, (size_t)N);
    zero_kernel<<<2048, 256>>>(rs_in_p,  (size_t)N);
    zero_kernel<<<8192, 256>>>(agg1_p,   (size_t)N * F_IN);
    zero_kernel<<<8192, 256>>>(agg2_p,   (size_t)N * C2);

    // 1) degrees -> rsqrt
    deg_kernel<<<(E + 255) / 256, 256>>>(src, dst, E, rs_out_p, rs_in_p);
    rsqrt_deg_kernel<<<(N + 255) / 256, 256>>>(rs_out_p, rs_in_p, N);

    // 2) conv1: aggregate x (64 feats) then GEMM (agg1 @ W1) * rs_in, leaky
    scatter1_kernel<<<(E + 7) / 8, 256>>>(x, ew, src, dst, rs_out_p, agg1_p, E);
    launch_sgemm(N, C1, F_IN, agg1_p, W1, g1_p, rs_in_p, 1);

    // 3) graphnorm1 (in place on g1)
    graphnorm_kernel<<<BATCH, 128, NODES * C1 * sizeof(float)>>>(
        g1_p, C1, a1, gm1, bt1, nullptr, 0);

    // 4) conv2: GEMM (g1 @ W2) * rs_out, then aggregate 96 feats
    launch_sgemm(N, C2, C1, g1_p, W2, h2_p, rs_out_p, 0);
    scatter2_kernel<<<(E + 7) / 8, 256>>>(h2_p, ew, src, dst, agg2_p, E);

    // 5) graphnorm2 with fused rs_in + leaky pre-op (in place on agg2)
    graphnorm_kernel<<<BATCH, 128, NODES * C2 * sizeof(float)>>>(
        agg2_p, C2, a2, gm2, bt2, rs_in_p, 1);

    // 6) MLP: [4096,6144] @ [6144,2048] -> leaky -> instnorm
    launch_sgemm(BATCH, HID, IN_MLP, agg2_p, Win, m1_p, nullptr, 1);
    instnorm_kernel<<<BATCH, 256>>>(m1_p, HID);

    // 7) [4096,2048] @ [2048,512] -> leaky -> instnorm
    launch_sgemm(BATCH, HID4, HID, m1_p, Whid, m2_p, nullptr, 1);
    instnorm_kernel<<<BATCH, 256>>>(m2_p, HID4);

    // 8) [4096,512] @ [512,256] -> output
    launch_sgemm(BATCH, OUTF, HID4, m2_p, Wcls, out, nullptr, 0);
}

// round 4
// speedup vs baseline: 2.7186x; 2.7186x over previous
#include <cuda_runtime.h>
#include <cuda_bf16.h>
#include <cstdint>
#include <math.h>

// ---------------------------------------------------------------------------
// Problem constants (fixed shapes from the dataset)
// ---------------------------------------------------------------------------
#define NN       262144      // total nodes
#define F_IN     64
#define C1       128
#define C2       96
#define BATCH    4096
#define NODES    64          // nodes per graph
#define IN_MLP   6144        // C2 * NODES
#define HID      2048
#define HID4     512
#define OUTF     256
#define NEG_SLOPE 0.01f
#define EPS      1e-5f

// ---------------------------------------------------------------------------
// Scratch (static device globals -- no allocation allowed)
// ---------------------------------------------------------------------------
__device__ float g_rs_out[NN];
__device__ float g_rs_in [NN];
__device__ float g_agg1  [(size_t)NN * F_IN];
__device__ float g_g1    [(size_t)NN * C1];
__device__ float g_h2    [(size_t)NN * C2];
__device__ float g_agg2  [(size_t)NN * C2];
__device__ float g_m1    [(size_t)BATCH * HID];
__device__ float g_m2    [(size_t)BATCH * HID4];
// transposed (tf32-rounded) weights
__device__ float g_W1T   [C1 * F_IN];
__device__ float g_W2T   [128 * C1];               // 96 padded to 128 rows
__device__ float g_WinT  [(size_t)HID * IN_MLP];
__device__ float g_WhidT [(size_t)HID4 * HID];

// ---------------------------------------------------------------------------
// PTX helpers
// ---------------------------------------------------------------------------
__device__ __forceinline__ uint32_t smem_u32(const void* p) {
    uint32_t r;
    asm("{ .reg .u64 t; cvta.to.shared.u64 t, %1; cvt.u32.u64 %0, t; }"
        : "=r"(r) : "l"(p));
    return r;
}

__device__ __forceinline__ float rna_tf32(float v) {
    uint32_t u;
    asm("cvt.rna.tf32.f32 %0, %1;" : "=r"(u) : "f"(v));
    return __uint_as_float(u);
}

__device__ __forceinline__ uint32_t rna_bits(float v) {
    uint32_t u;
    asm("cvt.rna.tf32.f32 %0, %1;" : "=r"(u) : "f"(v));
    return u;
}

__device__ __forceinline__ void cp_async16(uint32_t dst, const void* src) {
    asm volatile("cp.async.cg.shared.global [%0], [%1], 16;" :: "r"(dst), "l"(src));
}

__device__ __forceinline__ void mma_m16n8k8(float (&d)[4], const uint32_t (&a)[4],
                                            const uint32_t (&b)[2]) {
    asm volatile(
        "mma.sync.aligned.m16n8k8.row.col.f32.tf32.tf32.f32 "
        "{%0,%1,%2,%3}, {%4,%5,%6,%7}, {%8,%9}, {%0,%1,%2,%3};"
        : "+f"(d[0]), "+f"(d[1]), "+f"(d[2]), "+f"(d[3])
        : "r"(a[0]), "r"(a[1]), "r"(a[2]), "r"(a[3]), "r"(b[0]), "r"(b[1]));
}

// ---------------------------------------------------------------------------
// Utility kernels
// ---------------------------------------------------------------------------
__global__ void zero_kernel(float* __restrict__ p, size_t n) {
    size_t i = (size_t)blockIdx.x * blockDim.x + threadIdx.x;
    size_t stride = (size_t)gridDim.x * blockDim.x;
    for (; i < n; i += stride) p[i] = 0.0f;
}

__global__ void deg_kernel(const int* __restrict__ src, const int* __restrict__ dst,
                           int E, float* __restrict__ dout, float* __restrict__ din) {
    int i = blockIdx.x * blockDim.x + threadIdx.x;
    if (i < E) {
        atomicAdd(&dout[src[i]], 1.0f);
        atomicAdd(&din [dst[i]], 1.0f);
    }
}

__global__ void rsqrt_deg_kernel(float* __restrict__ a, float* __restrict__ b, int n) {
    int i = blockIdx.x * blockDim.x + threadIdx.x;
    if (i < n) {
        a[i] = rsqrtf(fmaxf(a[i], 1.0f));
        b[i] = rsqrtf(fmaxf(b[i], 1.0f));
    }
}

// Transpose in[R,C] -> out[C,R], rounding each value to tf32 (RNA).
__global__ void transpose_rna_kernel(const float* __restrict__ in, float* __restrict__ out,
                                     int R, int C) {
    __shared__ float t[32][33];
    int c0 = blockIdx.x * 32, r0 = blockIdx.y * 32;
    int x = threadIdx.x, y = threadIdx.y;   // block (32,8)
#pragma unroll
    for (int dy = 0; dy < 32; dy += 8) {
        int r = r0 + y + dy, c = c0 + x;
        float v = (r < R && c < C) ? in[(size_t)r * C + c] : 0.0f;
        t[y + dy][x] = rna_tf32(v);
    }
    __syncthreads();
#pragma unroll
    for (int dy = 0; dy < 32; dy += 8) {
        int oc = c0 + y + dy, orr = r0 + x;
        if (oc < C && orr < R) out[(size_t)oc * R + orr] = t[x][y + dy];
    }
}

// Scatter for conv1: agg1[dst] += x[src] * rs_out[src] * ew   (64 feats, one warp/edge)
__global__ void scatter1_kernel(const float* __restrict__ x, const float* __restrict__ ew,
                                const int* __restrict__ src, const int* __restrict__ dst,
                                const float* __restrict__ rs_out, float* __restrict__ agg,
                                int E) {
    int e = blockIdx.x * 8 + (threadIdx.x >> 5);
    if (e >= E) return;
    int lane = threadIdx.x & 31;
    int s = src[e], d = dst[e];
    float w = ew[e] * rs_out[s];
    float2 v = reinterpret_cast<const float2*>(x)[(size_t)s * 32 + lane];
    float* base = agg + (size_t)d * 64 + 2 * lane;
    atomicAdd(base,     v.x * w);
    atomicAdd(base + 1, v.y * w);
}

// Scatter for conv2: agg2[dst] += h2[src] * ew   (96 feats, one warp/edge)
__global__ void scatter2_kernel(const float* __restrict__ h, const float* __restrict__ ew,
                                const int* __restrict__ src, const int* __restrict__ dst,
                                float* __restrict__ agg, int E) {
    int e = blockIdx.x * 8 + (threadIdx.x >> 5);
    if (e >= E) return;
    int lane = threadIdx.x & 31;
    int s = src[e], d = dst[e];
    float w = ew[e];
    const float* hp = h + (size_t)s * 96;
    float* ap = agg + (size_t)d * 96;
#pragma unroll
    for (int i = 0; i < 3; i++) {
        int c = lane + 32 * i;
        atomicAdd(&ap[c], hp[c] * w);
    }
}

// ---------------------------------------------------------------------------
// tf32 mma.sync GEMM: C[M,Nout] = A[M,K] @ BT[Npad,K]^T
//   CTA tile 256x128, BK=32, 8 warps (4x2), warp tile 64x64.
//   3-stage cp.async pipeline, stride-36 smem rows (conflict-free frag loads).
//   A fragments RNA-rounded to tf32 in-kernel; BT pre-rounded.
//   Requires: M % 256 == 0, K % 32 == 0, BT zero-padded to gridDim.x*128 rows.
// ---------------------------------------------------------------------------
#define GBM 256
#define GBN 128
#define GBK 32
#define GSTR 36                         // smem row stride in floats (144 B)
#define A_STAGE_F (GBM * GSTR)          // 9216 floats
#define B_STAGE_F (GBN * GSTR)          // 4608 floats
#define STAGE_F   (A_STAGE_F + B_STAGE_F)
#define STAGE_B   (STAGE_F * 4)         // 55296 bytes
#define GEMM_SMEM (3 * STAGE_B)         // 165888 bytes

__device__ __forceinline__ void gemm_load_stage(const float* __restrict__ A,
                                                const float* __restrict__ BT,
                                                int K, int m0, int n0, int k0,
                                                uint32_t sbuf, int tid) {
    const uint32_t sA = sbuf;
    const uint32_t sB = sbuf + A_STAGE_F * 4;
#pragma unroll
    for (int p = 0; p < 8; p++) {           // A: 256 rows x 32 floats
        int id = tid + (p << 8);
        int r = id >> 3, c = id & 7;
        cp_async16(sA + r * 144 + c * 16, A + (size_t)(m0 + r) * K + k0 + c * 4);
    }
#pragma unroll
    for (int p = 0; p < 4; p++) {           // B: 128 rows x 32 floats
        int id = tid + (p << 8);
        int r = id >> 3, c = id & 7;
        cp_async16(sB + r * 144 + c * 16, BT + (size_t)(n0 + r) * K + k0 + c * 4);
    }
}

__global__ __launch_bounds__(256, 1)
void mma_gemm_kernel(int M, int K, int Nout,
                     const float* __restrict__ A, const float* __restrict__ BT,
                     float* __restrict__ C,
                     const float* __restrict__ rowscale, int do_leaky) {
    extern __shared__ float dynsm[];
    const uint32_t sbase = smem_u32(dynsm);

    const int tid    = threadIdx.x;
    const int wid    = tid >> 5;
    const int lane   = tid & 31;
    const int warp_m = wid & 3;     // 4 warp rows of 64
    const int warp_n = wid >> 2;    // 2 warp cols of 64
    const int m0 = blockIdx.y * GBM;
    const int n0 = blockIdx.x * GBN;

    float acc[4][8][4];
#pragma unroll
    for (int mt = 0; mt < 4; mt++)
#pragma unroll
        for (int nt = 0; nt < 8; nt++)
#pragma unroll
            for (int j = 0; j < 4; j++) acc[mt][nt][j] = 0.0f;

    const int T = K / GBK;

    // prologue: stages 0 and 1
#pragma unroll
    for (int s = 0; s < 2; s++) {
        if (s < T) gemm_load_stage(A, BT, K, m0, n0, s * GBK, sbase + s * STAGE_B, tid);
        asm volatile("cp.async.commit_group;" ::: "memory");
    }

    for (int i = 0; i < T; i++) {
        if (i + 1 < T)
            asm volatile("cp.async.wait_group 1;" ::: "memory");
        else
            asm volatile("cp.async.wait_group 0;" ::: "memory");
        __syncthreads();

        // prefetch stage i+2 into buffer (i+2)%3 (held stage i-1, already consumed)
        if (i + 2 < T)
            gemm_load_stage(A, BT, K, m0, n0, (i + 2) * GBK,
                            sbase + ((i + 2) % 3) * STAGE_B, tid);
        asm volatile("cp.async.commit_group;" ::: "memory");

        const float* As = dynsm + (i % 3) * STAGE_F;
        const float* Bs = As + A_STAGE_F;

#pragma unroll
        for (int kk = 0; kk < 4; kk++) {
            uint32_t af[4][4];
            uint32_t bf[8][2];
            const int klo = kk * 8 + (lane & 3);
#pragma unroll
            for (int mt = 0; mt < 4; mt++) {
                const int row = warp_m * 64 + mt * 16 + (lane >> 2);
                const float* ap = As + row * GSTR + klo;
                af[mt][0] = rna_bits(ap[0]);
                af[mt][1] = rna_bits(ap[8 * GSTR]);
                af[mt][2] = rna_bits(ap[4]);
                af[mt][3] = rna_bits(ap[8 * GSTR + 4]);
            }
#pragma unroll
            for (int nt = 0; nt < 8; nt++) {
                const int col = warp_n * 64 + nt * 8 + (lane >> 2);
                const float* bp = Bs + col * GSTR + klo;
                bf[nt][0] = __float_as_uint(bp[0]);
                bf[nt][1] = __float_as_uint(bp[4]);
            }
#pragma unroll
            for (int mt = 0; mt < 4; mt++)
#pragma unroll
                for (int nt = 0; nt < 8; nt++)
                    mma_m16n8k8(acc[mt][nt], af[mt], bf[nt]);
        }
    }

    // epilogue: rowscale + optional leaky, float2 stores, column-guarded
#pragma unroll
    for (int mt = 0; mt < 4; mt++) {
        const int r0 = m0 + warp_m * 64 + mt * 16 + (lane >> 2);
        const int r1 = r0 + 8;
        const float s0 = rowscale ? rowscale[r0] : 1.0f;
        const float s1 = rowscale ? rowscale[r1] : 1.0f;
#pragma unroll
        for (int nt = 0; nt < 8; nt++) {
            const int c = n0 + warp_n * 64 + nt * 8 + (lane & 3) * 2;
            if (c < Nout) {
                float v0 = acc[mt][nt][0] * s0;
                float v1 = acc[mt][nt][1] * s0;
                float v2 = acc[mt][nt][2] * s1;
                float v3 = acc[mt][nt][3] * s1;
                if (do_leaky) {
                    v0 = (v0 >= 0.0f) ? v0 : NEG_SLOPE * v0;
                    v1 = (v1 >= 0.0f) ? v1 : NEG_SLOPE * v1;
                    v2 = (v2 >= 0.0f) ? v2 : NEG_SLOPE * v2;
                    v3 = (v3 >= 0.0f) ? v3 : NEG_SLOPE * v3;
                }
                *reinterpret_cast<float2*>(C + (size_t)r0 * Nout + c) = make_float2(v0, v1);
                *reinterpret_cast<float2*>(C + (size_t)r1 * Nout + c) = make_float2(v2, v3);
            }
        }
    }
}

// ---------------------------------------------------------------------------
// fp32 SGEMM (final small GEMM -> output fidelity)
// ---------------------------------------------------------------------------
__global__ __launch_bounds__(256)
void sgemm_kernel(int M, int N, int K,
                  const float* __restrict__ A, const float* __restrict__ B,
                  float* __restrict__ C,
                  const float* __restrict__ rowscale, int do_leaky) {
    const int BM = 128, BN = 128, BK = 8, TM = 8, TN = 8;
    __shared__ float As[BK][BM];
    __shared__ float Bs[BK][BN];

    int tid = threadIdx.x;
    int block_row = blockIdx.y * BM;
    int block_col = blockIdx.x * BN;
    int trow = (tid / (BN / TN)) * TM;
    int tcol = (tid % (BN / TN)) * TN;

    float acc[TM][TN];
#pragma unroll
    for (int i = 0; i < TM; i++)
#pragma unroll
        for (int j = 0; j < TN; j++) acc[i][j] = 0.0f;

    int arow = tid >> 1;
    int acol0 = (tid & 1) * 4;
    int brow = tid >> 5;
    int bcol0 = (tid & 31) * 4;
    float ra[TM], rb[TN];

    for (int k0 = 0; k0 < K; k0 += BK) {
        {
            int gr = block_row + arow;
#pragma unroll
            for (int i = 0; i < 4; i++) {
                int gc = k0 + acol0 + i;
                float v = 0.0f;
                if (gr < M && gc < K) v = A[(size_t)gr * K + gc];
                As[acol0 + i][arow] = v;
            }
        }
        {
            int gr = k0 + brow;
#pragma unroll
            for (int i = 0; i < 4; i++) {
                int gc = block_col + bcol0 + i;
                float v = 0.0f;
                if (gr < K && gc < N) v = B[(size_t)gr * N + gc];
                Bs[brow][bcol0 + i] = v;
            }
        }
        __syncthreads();
#pragma unroll
        for (int kk = 0; kk < BK; kk++) {
#pragma unroll
            for (int i = 0; i < TM; i++) ra[i] = As[kk][trow + i];
#pragma unroll
            for (int j = 0; j < TN; j++) rb[j] = Bs[kk][tcol + j];
#pragma unroll
            for (int i = 0; i < TM; i++)
#pragma unroll
                for (int j = 0; j < TN; j++)
                    acc[i][j] = fmaf(ra[i], rb[j], acc[i][j]);
        }
        __syncthreads();
    }

#pragma unroll
    for (int i = 0; i < TM; i++) {
        int gr = block_row + trow + i;
        if (gr >= M) continue;
        float s = rowscale ? rowscale[gr] : 1.0f;
#pragma unroll
        for (int j = 0; j < TN; j++) {
            int gc = block_col + tcol + j;
            if (gc >= N) continue;
            float v = acc[i][j] * s;
            if (do_leaky) v = (v >= 0.0f) ? v : NEG_SLOPE * v;
            C[(size_t)gr * N + gc] = v;
        }
    }
}

// ---------------------------------------------------------------------------
// GraphNorm: one block per graph (64 nodes x C channels), in place.
// ---------------------------------------------------------------------------
__global__ void graphnorm_kernel(float* __restrict__ h, int C,
                                 const float* __restrict__ alpha,
                                 const float* __restrict__ gamma,
                                 const float* __restrict__ beta,
                                 const float* __restrict__ rs_in, int pre_leaky,
                                 int rna_out) {
    extern __shared__ float dynsm[];
    float* sm = dynsm;
    int g = blockIdx.x;
    float* base = h + (size_t)g * NODES * C;
    int tid = threadIdx.x;

    for (int idx = tid; idx < NODES * C; idx += blockDim.x) {
        int r = idx / C;
        float v = base[idx];
        if (rs_in) v *= rs_in[g * NODES + r];
        if (pre_leaky) v = (v >= 0.0f) ? v : NEG_SLOPE * v;
        sm[idx] = v;
    }
    __syncthreads();

    for (int c = tid; c < C; c += blockDim.x) {
        float sum = 0.0f;
#pragma unroll 8
        for (int r = 0; r < NODES; r++) sum += sm[r * C + c];
        float mean = sum * (1.0f / NODES);
        float am = alpha[c] * mean;
        float var = 0.0f;
#pragma unroll 8
        for (int r = 0; r < NODES; r++) {
            float s = sm[r * C + c] - am;
            var += s * s;
        }
        var *= (1.0f / NODES);
        float inv = rsqrtf(var + EPS);
        float gmm = gamma[c], bt = beta[c];
        for (int r = 0; r < NODES; r++) {
            float v = gmm * (sm[r * C + c] - am) * inv + bt;
            base[r * C + c] = rna_out ? rna_tf32(v) : v;
        }
    }
}

// ---------------------------------------------------------------------------
// InstanceNorm1d (affine=False) per row, in place. One block per row.
// ---------------------------------------------------------------------------
__global__ void instnorm_kernel(float* __restrict__ h, int C, int rna_out) {
    int row = blockIdx.x;
    float* p = h + (size_t)row * C;
    int tid = threadIdx.x;

    float s = 0.0f, q = 0.0f;
    for (int c = tid; c < C; c += blockDim.x) {
        float v = p[c];
        s += v; q += v * v;
    }
    __shared__ float ss[32], sq[32];
#pragma unroll
    for (int o = 16; o; o >>= 1) {
        s += __shfl_xor_sync(0xffffffffu, s, o);
        q += __shfl_xor_sync(0xffffffffu, q, o);
    }
    if ((tid & 31) == 0) { ss[tid >> 5] = s; sq[tid >> 5] = q; }
    __syncthreads();
    int nwarp = blockDim.x >> 5;
    if (tid < 32) {
        s = (tid < nwarp) ? ss[tid] : 0.0f;
        q = (tid < nwarp) ? sq[tid] : 0.0f;
#pragma unroll
        for (int o = 16; o; o >>= 1) {
            s += __shfl_xor_sync(0xffffffffu, s, o);
            q += __shfl_xor_sync(0xffffffffu, q, o);
        }
        if (tid == 0) { ss[0] = s; sq[0] = q; }
    }
    __syncthreads();
    float mean = ss[0] / C;
    float var = sq[0] / C - mean * mean;
    float inv = rsqrtf(var + EPS);
    for (int c = tid; c < C; c += blockDim.x) {
        float v = (p[c] - mean) * inv;
        p[c] = rna_out ? rna_tf32(v) : v;
    }
}

// ---------------------------------------------------------------------------
// Launch
// ---------------------------------------------------------------------------
static void launch_tf32(int M, int K, int Nout, const float* A, const float* BT,
                        float* C, const float* rowscale, int do_leaky) {
    dim3 grid((Nout + GBN - 1) / GBN, M / GBM);
    mma_gemm_kernel<<<grid, 256, GEMM_SMEM>>>(M, K, Nout, A, BT, C, rowscale, do_leaky);
}

extern "C" void kernel_launch(void* const* d_in, const int* in_sizes, int n_in,
                              void* d_out, int out_size) {
    const float* x    = (const float*)d_in[0];
    const float* ew   = (const float*)d_in[1];
    const int*   src  = (const int*)  d_in[2];
    const int*   dst  = (const int*)  d_in[3];
    const float* W1   = (const float*)d_in[4];
    const float* W2   = (const float*)d_in[5];
    const float* a1   = (const float*)d_in[6];
    const float* gm1  = (const float*)d_in[7];
    const float* bt1  = (const float*)d_in[8];
    const float* a2   = (const float*)d_in[9];
    const float* gm2  = (const float*)d_in[10];
    const float* bt2  = (const float*)d_in[11];
    const float* Win  = (const float*)d_in[12];
    const float* Whid = (const float*)d_in[13];
    const float* Wcls = (const float*)d_in[14];
    float* out = (float*)d_out;

    const int E = in_sizes[1];
    const int N = in_sizes[0] / F_IN;

    float *rs_out_p, *rs_in_p, *agg1_p, *g1_p, *h2_p, *agg2_p, *m1_p, *m2_p;
    float *w1t_p, *w2t_p, *wint_p, *whidt_p;
    cudaGetSymbolAddress((void**)&rs_out_p, g_rs_out);
    cudaGetSymbolAddress((void**)&rs_in_p,  g_rs_in);
    cudaGetSymbolAddress((void**)&agg1_p,   g_agg1);
    cudaGetSymbolAddress((void**)&g1_p,     g_g1);
    cudaGetSymbolAddress((void**)&h2_p,     g_h2);
    cudaGetSymbolAddress((void**)&agg2_p,   g_agg2);
    cudaGetSymbolAddress((void**)&m1_p,     g_m1);
    cudaGetSymbolAddress((void**)&m2_p,     g_m2);
    cudaGetSymbolAddress((void**)&w1t_p,    g_W1T);
    cudaGetSymbolAddress((void**)&w2t_p,    g_W2T);
    cudaGetSymbolAddress((void**)&wint_p,   g_WinT);
    cudaGetSymbolAddress((void**)&whidt_p,  g_WhidT);

    cudaFuncSetAttribute(mma_gemm_kernel,
                         cudaFuncAttributeMaxDynamicSharedMemorySize, GEMM_SMEM);

    // 0) zero accumulators + padded weight scratch
    zero_kernel<<<2048, 256>>>(rs_out_p, (size_t)N);
    zero_kernel<<<2048, 256>>>(rs_in_p,  (size_t)N);
    zero_kernel<<<8192, 256>>>(agg1_p,   (size_t)N * F_IN);
    zero_kernel<<<8192, 256>>>(agg2_p,   (size_t)N * C2);
    zero_kernel<<<64,   256>>>(w2t_p,    (size_t)128 * C1);

    // 1) transpose + tf32-round weights
    {
        dim3 b(32, 8);
        transpose_rna_kernel<<<dim3((C1 + 31) / 32, (F_IN + 31) / 32), b>>>(W1, w1t_p, F_IN, C1);
        transpose_rna_kernel<<<dim3((C2 + 31) / 32, (C1 + 31) / 32), b>>>(W2, w2t_p, C1, C2);
        transpose_rna_kernel<<<dim3((HID + 31) / 32, (IN_MLP + 31) / 32), b>>>(Win, wint_p, IN_MLP, HID);
        transpose_rna_kernel<<<dim3((HID4 + 31) / 32, (HID + 31) / 32), b>>>(Whid, whidt_p, HID, HID4);
    }

    // 2) degrees -> rsqrt
    deg_kernel<<<(E + 255) / 256, 256>>>(src, dst, E, rs_out_p, rs_in_p);
    rsqrt_deg_kernel<<<(N + 255) / 256, 256>>>(rs_out_p, rs_in_p, N);

    // 3) conv1: aggregate x (64 feats) then tf32 GEMM (agg1 @ W1) * rs_in, leaky
    scatter1_kernel<<<(E + 7) / 8, 256>>>(x, ew, src, dst, rs_out_p, agg1_p, E);
    launch_tf32(N, F_IN, C1, agg1_p, w1t_p, g1_p, rs_in_p, 1);

    // 4) graphnorm1 (in place, tf32-rounded output)
    graphnorm_kernel<<<BATCH, 128, NODES * C1 * sizeof(float)>>>(
        g1_p, C1, a1, gm1, bt1, nullptr, 0, 1);

    // 5) conv2: tf32 GEMM (g1 @ W2) * rs_out, then aggregate 96 feats
    launch_tf32(N, C1, C2, g1_p, w2t_p, h2_p, rs_out_p, 0);
    scatter2_kernel<<<(E + 7) / 8, 256>>>(h2_p, ew, src, dst, agg2_p, E);

    // 6) graphnorm2 with fused rs_in + leaky pre-op (tf32-rounded output)
    graphnorm_kernel<<<BATCH, 128, NODES * C2 * sizeof(float)>>>(
        agg2_p, C2, a2, gm2, bt2, rs_in_p, 1, 1);

    // 7) MLP1 (tf32): [4096,6144] @ [6144,2048] -> leaky -> instnorm (rounded)
    launch_tf32(BATCH, IN_MLP, HID, agg2_p, wint_p, m1_p, nullptr, 1);
    instnorm_kernel<<<BATCH, 256>>>(m1_p, HID, 1);

    // 8) MLP2 (tf32): [4096,2048] @ [2048,512] -> leaky -> instnorm
    launch_tf32(BATCH, HID, HID4, m1_p, whidt_p, m2_p, nullptr, 1);
    instnorm_kernel<<<BATCH, 256>>>(m2_p, HID4, 0);

    // 9) MLP3 (fp32, output fidelity): [4096,512] @ [512,256]
    {
        dim3 grid((OUTF + 127) / 128, (BATCH + 127) / 128);
        sgemm_kernel<<<grid, 256>>>(BATCH, OUTF, HID4, m2_p, Wcls, out, nullptr, 0);
    }
}